// round 15
// baseline (speedup 1.0000x reference)
#include <cuda_runtime.h>
#include <cuda_bf16.h>

// ---------------------------------------------------------------------------
// G2EquivariantFeedForward, GB300 sm_103a — round 15
//
// Closed form: upd = a*x + b*x^2 + c*x^3 = (P, Q*v) for x = r + v,
//   P = a*r + b*(r^2-n^2) + c*r*(r^2-3n^2)
//   Q = a + 2*b*r + c*(3r^2-n^2),  n^2=|v|^2,  |upd|^2 = P^2 + Q^2 n^2
//
// Round 15 = round 8 (best: NS=2 f32x2 streams, full unroll, constant-port
// tables, 57.8us) + two low-risk changes:
//   1. PERSISTENT grid: 1184 blocks (148 SMs x 8 resident), guarded
//      grid-stride over the 8192 tiles -> no CTA refill / wave-transition
//      overhead, perfectly balanced (6-7 tiles/block).
//   2. f32x2 epilogue scaling via register-pair aliasing (ulonglong2
//      re-load, mul2 by splatted K) — moves ~12 slots/thread from the
//      BINDING fma pipe to the idle alu pipe.
// ---------------------------------------------------------------------------

typedef unsigned long long U64;

__device__ __forceinline__ U64 pk2(float lo, float hi) {
    U64 r; asm("mov.b64 %0, {%1, %2};" : "=l"(r) : "f"(lo), "f"(hi)); return r;
}
__device__ __forceinline__ void upk2(U64 v, float& lo, float& hi) {
    asm("mov.b64 {%0, %1}, %2;" : "=f"(lo), "=f"(hi) : "l"(v));
}
__device__ __forceinline__ U64 fma2(U64 a, U64 b, U64 c) {
    U64 d; asm("fma.rn.f32x2 %0, %1, %2, %3;" : "=l"(d) : "l"(a), "l"(b), "l"(c)); return d;
}
__device__ __forceinline__ U64 mul2(U64 a, U64 b) {
    U64 d; asm("mul.rn.f32x2 %0, %1, %2;" : "=l"(d) : "l"(a), "l"(b)); return d;
}
__device__ __forceinline__ U64 add2(U64 a, U64 b) {
    U64 d; asm("add.rn.f32x2 %0, %1, %2;" : "=l"(d) : "l"(a), "l"(b)); return d;
}
__device__ __forceinline__ float tanh_ap(float x) {
    float t; asm("tanh.approx.f32 %0, %1;" : "=f"(t) : "f"(x)); return t;
}
__device__ __forceinline__ float sqrt_ap(float x) {
    float t; asm("sqrt.approx.f32 %0, %1;" : "=f"(t) : "f"(x)); return t;
}
__device__ __forceinline__ float rsqrt_ap(float x) {
    float t; asm("rsqrt.approx.f32 %0, %1;" : "=f"(t) : "f"(x)); return t;
}

__device__ __forceinline__ float norm2_imag(const float4& a0, const float4& a1) {
    float n = a0.y * a0.y;
    n = fmaf(a0.z, a0.z, n);
    n = fmaf(a0.w, a0.w, n);
    n = fmaf(a1.x, a1.x, n);
    n = fmaf(a1.y, a1.y, n);
    n = fmaf(a1.z, a1.z, n);
    n = fmaf(a1.w, a1.w, n);
    return n;
}

// ---- packed weight tables: built on device, then copied into __constant__ ----
struct __align__(16) CTab {
    ulonglong2 W1[32];   // (w0,w0 | w1,w1)
    ulonglong2 BW[32];   // (b1,b1 | 0.5*w2c,0.5*w2c)
    ulonglong2 W2[32];   // (0.5*w2a,.. | 0.5*w2b,..)
    U64        B2[3];    // (b2k, b2k)
    float      scal[2];  // lam, 1-lam
};

__device__   CTab dScratch;   // written by prep kernel
__constant__ CTab cT;         // read by main kernel (constant port)

__global__ void prep_kernel(const float* __restrict__ W1,
                            const float* __restrict__ b1,
                            const float* __restrict__ W2,
                            const float* __restrict__ b2,
                            const float* __restrict__ alpha)
{
    const int t = threadIdx.x;     // 32 threads
    float w0 = W1[2 * t], w1 = W1[2 * t + 1];
    ulonglong2 q; q.x = pk2(w0, w0); q.y = pk2(w1, w1);
    dScratch.W1[t] = q;
    float bb = b1[t], wc = 0.5f * W2[64 + t];
    ulonglong2 qb; qb.x = pk2(bb, bb); qb.y = pk2(wc, wc);
    dScratch.BW[t] = qb;
    float wa = 0.5f * W2[t], wb = 0.5f * W2[32 + t];
    ulonglong2 q2; q2.x = pk2(wa, wa); q2.y = pk2(wb, wb);
    dScratch.W2[t] = q2;
    if (t == 0) {
        float al  = alpha[0];
        float lam = 1.0f / (1.0f + __expf(-al));
        dScratch.scal[0] = lam;
        dScratch.scal[1] = 1.0f - lam;
        dScratch.B2[0] = pk2(b2[0], b2[0]);
        dScratch.B2[1] = pk2(b2[1], b2[1]);
        dScratch.B2[2] = pk2(b2[2], b2[2]);
    }
}

#define TPB   128        // threads per block
#define OPB   512        // octonions per tile (4 per thread)
#define GRIDP 1184       // persistent blocks = 148 SMs x 8 resident

// f32x2 epilogue scaling for one octonion (2x ulonglong2 = 8 floats).
// lo lane of first pair is replaced by the new scalar component o0.
__device__ __forceinline__ void scale_store(const ulonglong2* __restrict__ in8,
                                            ulonglong2* __restrict__ out8,
                                            int m, float K, float o0)
{
    U64 KK = pk2(K, K);
    ulonglong2 v0 = in8[2 * m + 0];
    ulonglong2 v1 = in8[2 * m + 1];
    U64 s0 = mul2(v0.x, KK);
    U64 s1 = mul2(v0.y, KK);
    U64 s2 = mul2(v1.x, KK);
    U64 s3 = mul2(v1.y, KK);
    float d0, d1; upk2(s0, d0, d1);      // d1 = p1*K (keep), d0 discarded
    ulonglong2 o0p; o0p.x = pk2(o0, d1); o0p.y = s1;
    ulonglong2 o1p; o1p.x = s2;          o1p.y = s3;
    out8[2 * m + 0] = o0p;
    out8[2 * m + 1] = o1p;
}

__global__ __launch_bounds__(TPB, 8)
void g2ff_kernel(const float4* __restrict__ in4,
                 float4*       __restrict__ out4,
                 int nTiles)
{
    const int t = threadIdx.x;
    const ulonglong2* in8  = (const ulonglong2*)in4;
    ulonglong2*       out8 = (ulonglong2*)out4;

    // GELU-tanh constants
    const U64 C1 = pk2(0.7978845608028654f, 0.7978845608028654f);
    const U64 C2 = pk2(0.035677408136300125f, 0.035677408136300125f);
    const U64 N1  = pk2(-1.0f, -1.0f);
    const U64 N3  = pk2(-3.0f, -3.0f);
    const U64 TWO = pk2(2.0f, 2.0f);
    const float lam = cT.scal[0], oml = cT.scal[1];
    const U64 LAM = pk2(lam, lam);
    const U64 OML = pk2(oml, oml);

    for (int tile = blockIdx.x; tile < nTiles; tile += GRIDP) {
        const int base = tile * OPB;
        const int mA = base + t;
        const int mB = base + TPB + t;
        const int mC = base + 2 * TPB + t;
        const int mD = base + 3 * TPB + t;

        // ---- prologue: scalar n^2 per octonion; pack only (r, np) pairs ----
        U64 Xp0, Xnp, Yp0, Ynp;
        {
            float4 a0 = in4[2 * mA + 0];
            float4 a1 = in4[2 * mA + 1];
            float4 b0 = in4[2 * mB + 0];
            float4 b1v = in4[2 * mB + 1];
            float nA = norm2_imag(a0, a1);
            float nB = norm2_imag(b0, b1v);
            Xp0 = pk2(a0.x, b0.x);
            Xnp = pk2(sqrt_ap(nA), sqrt_ap(nB));
        }
        {
            float4 a0 = in4[2 * mC + 0];
            float4 a1 = in4[2 * mC + 1];
            float4 b0 = in4[2 * mD + 0];
            float4 b1v = in4[2 * mD + 1];
            float nA = norm2_imag(a0, a1);
            float nB = norm2_imag(b0, b1v);
            Yp0 = pk2(a0.x, b0.x);
            Ynp = pk2(sqrt_ap(nA), sqrt_ap(nB));
        }

        U64 aAX = cT.B2[0], aBX = cT.B2[1], aCX = cT.B2[2];
        U64 aAY = cT.B2[0], aBY = cT.B2[1], aCY = cT.B2[2];

#pragma unroll
        for (int j = 0; j < 32; j++) {
            ulonglong2 w1j = cT.W1[j];   // LDC.128 (constant port)
            ulonglong2 bwj = cT.BW[j];
            ulonglong2 w2j = cT.W2[j];

            // stream X:  h' = z*(1+tanh(u)) = 2*gelu(z); W2 pre-halved
            {
                U64 z  = fma2(Xnp, w1j.y, fma2(Xp0, w1j.x, bwj.x));
                U64 z2 = mul2(z, z);
                U64 qq = fma2(z2, C2, C1);
                U64 u  = mul2(z, qq);
                float ul, uh; upk2(u, ul, uh);
                U64 tt = pk2(tanh_ap(ul), tanh_ap(uh));
                U64 h  = fma2(z, tt, z);
                aAX = fma2(h, w2j.x, aAX);
                aBX = fma2(h, w2j.y, aBX);
                aCX = fma2(h, bwj.y, aCX);
            }
            // stream Y
            {
                U64 z  = fma2(Ynp, w1j.y, fma2(Yp0, w1j.x, bwj.x));
                U64 z2 = mul2(z, z);
                U64 qq = fma2(z2, C2, C1);
                U64 u  = mul2(z, qq);
                float ul, uh; upk2(u, ul, uh);
                U64 tt = pk2(tanh_ap(ul), tanh_ap(uh));
                U64 h  = fma2(z, tt, z);
                aAY = fma2(h, w2j.x, aAY);
                aBY = fma2(h, w2j.y, aBY);
                aCY = fma2(h, bwj.y, aCY);
            }
        }

        // ---- epilogue stream X ----
        {
            U64 n2 = mul2(Xnp, Xnp);
            U64 r2 = mul2(Xp0, Xp0);
            U64 s2 = fma2(n2, N1, r2);
            U64 u3 = fma2(n2, N3, r2);
            U64 s3 = mul2(Xp0, u3);
            U64 t3 = fma2(r2, TWO, s2);
            U64 P  = fma2(aAX, Xp0, fma2(aBX, s2, mul2(aCX, s3)));
            U64 tr = add2(Xp0, Xp0);
            U64 Q  = fma2(aCX, t3, fma2(aBX, tr, aAX));
            U64 ss = fma2(mul2(Q, Q), n2, mul2(P, P));
            float sl, sh; upk2(ss, sl, sh);
            sl = fmaxf(sl, 1e-16f);
            sh = fmaxf(sh, 1e-16f);
            U64 inv = pk2(rsqrt_ap(sl), rsqrt_ap(sh));
            U64 li  = mul2(LAM, inv);
            U64 K   = fma2(li, Q, OML);
            U64 o0  = fma2(li, P, mul2(Xp0, OML));
            float Klo, Khi; upk2(K, Klo, Khi);
            float olo, ohi; upk2(o0, olo, ohi);
            scale_store(in8, out8, mA, Klo, olo);
            scale_store(in8, out8, mB, Khi, ohi);
        }
        // ---- epilogue stream Y ----
        {
            U64 n2 = mul2(Ynp, Ynp);
            U64 r2 = mul2(Yp0, Yp0);
            U64 s2 = fma2(n2, N1, r2);
            U64 u3 = fma2(n2, N3, r2);
            U64 s3 = mul2(Yp0, u3);
            U64 t3 = fma2(r2, TWO, s2);
            U64 P  = fma2(aAY, Yp0, fma2(aBY, s2, mul2(aCY, s3)));
            U64 tr = add2(Yp0, Yp0);
            U64 Q  = fma2(aCY, t3, fma2(aBY, tr, aAY));
            U64 ss = fma2(mul2(Q, Q), n2, mul2(P, P));
            float sl, sh; upk2(ss, sl, sh);
            sl = fmaxf(sl, 1e-16f);
            sh = fmaxf(sh, 1e-16f);
            U64 inv = pk2(rsqrt_ap(sl), rsqrt_ap(sh));
            U64 li  = mul2(LAM, inv);
            U64 K   = fma2(li, Q, OML);
            U64 o0  = fma2(li, P, mul2(Yp0, OML));
            float Klo, Khi; upk2(K, Klo, Khi);
            float olo, ohi; upk2(o0, olo, ohi);
            scale_store(in8, out8, mC, Klo, olo);
            scale_store(in8, out8, mD, Khi, ohi);
        }
    }
}

extern "C" void kernel_launch(void* const* d_in, const int* in_sizes, int n_in,
                              void* d_out, int out_size)
{
    const float* o     = (const float*)d_in[0];
    const float* W1    = (const float*)d_in[1];
    const float* b1    = (const float*)d_in[2];
    const float* W2    = (const float*)d_in[3];
    const float* b2    = (const float*)d_in[4];
    const float* alpha = (const float*)d_in[5];

    // 1) pack weight tables on device
    prep_kernel<<<1, 32>>>(W1, b1, W2, b2, alpha);

    // 2) copy packed tables into __constant__ (D2D memcpy node, capturable)
    void* scratch_addr = nullptr;
    cudaGetSymbolAddress(&scratch_addr, dScratch);
    cudaMemcpyToSymbolAsync(cT, scratch_addr, sizeof(CTab), 0,
                            cudaMemcpyDeviceToDevice);

    // 3) persistent main kernel
    const int total  = in_sizes[0];         // 33,554,432 floats
    const int octs   = total / 8;           // 4,194,304 octonions
    const int nTiles = octs / OPB;          // 8192
    const int blocks = (nTiles < GRIDP) ? nTiles : GRIDP;

    g2ff_kernel<<<blocks, TPB>>>((const float4*)o, (float4*)d_out, nTiles);
}

// round 16
// speedup vs baseline: 1.0990x; 1.0990x over previous
#include <cuda_runtime.h>
#include <cuda_bf16.h>

// ---------------------------------------------------------------------------
// G2EquivariantFeedForward, GB300 sm_103a — FINAL (= round 8, measured best)
//
// Closed form: for octonion x = r + v (v pure imaginary),
//   x^2 = (r^2 - n^2, 2r v),  x^3 = (r(r^2-3n^2), (3r^2-n^2) v),  n^2 = |v|^2
//   upd = a x + b x^2 + c x^3 = (P, Q v)
//   P = a r + b (r^2-n^2) + c r (r^2-3n^2)
//   Q = a + 2 b r + c (3r^2-n^2),       |upd|^2 = P^2 + Q^2 n^2
//
// Structure (each element validated by a bracketing experiment):
//   - 4 octonions/thread as TWO f32x2 lane-packed streams (NS=2 is the
//     issued-slot minimum: NS=1 pays the LDC floor + fixed overhead, NS=4
//     kills occupancy)
//   - weight tables splat-packed on device (prep kernel) and copied into
//     __constant__ (graph-capturable D2D memcpyToSymbol); loop reads go
//     through the constant port, keeping L1tex at ~32%
//   - GELU(erf) ~ tanh form via MUFU.TANH, 0.5 folded into W2 tables
//   - epilogue re-loads octonions from global (L2 hit) and scales scalar
//     components; loop-live state is just (p0, np) per stream
//   - FULL unroll + __launch_bounds__(128,8): 61 regs, no spills; partial
//     unroll / tighter caps / port splits / persistent grids all measured
//     worse (R9-R15)
// ---------------------------------------------------------------------------

typedef unsigned long long U64;

__device__ __forceinline__ U64 pk2(float lo, float hi) {
    U64 r; asm("mov.b64 %0, {%1, %2};" : "=l"(r) : "f"(lo), "f"(hi)); return r;
}
__device__ __forceinline__ void upk2(U64 v, float& lo, float& hi) {
    asm("mov.b64 {%0, %1}, %2;" : "=f"(lo), "=f"(hi) : "l"(v));
}
__device__ __forceinline__ U64 fma2(U64 a, U64 b, U64 c) {
    U64 d; asm("fma.rn.f32x2 %0, %1, %2, %3;" : "=l"(d) : "l"(a), "l"(b), "l"(c)); return d;
}
__device__ __forceinline__ U64 mul2(U64 a, U64 b) {
    U64 d; asm("mul.rn.f32x2 %0, %1, %2;" : "=l"(d) : "l"(a), "l"(b)); return d;
}
__device__ __forceinline__ U64 add2(U64 a, U64 b) {
    U64 d; asm("add.rn.f32x2 %0, %1, %2;" : "=l"(d) : "l"(a), "l"(b)); return d;
}
__device__ __forceinline__ float tanh_ap(float x) {
    float t; asm("tanh.approx.f32 %0, %1;" : "=f"(t) : "f"(x)); return t;
}
__device__ __forceinline__ float sqrt_ap(float x) {
    float t; asm("sqrt.approx.f32 %0, %1;" : "=f"(t) : "f"(x)); return t;
}
__device__ __forceinline__ float rsqrt_ap(float x) {
    float t; asm("rsqrt.approx.f32 %0, %1;" : "=f"(t) : "f"(x)); return t;
}

__device__ __forceinline__ float norm2_imag(const float4& a0, const float4& a1) {
    float n = a0.y * a0.y;
    n = fmaf(a0.z, a0.z, n);
    n = fmaf(a0.w, a0.w, n);
    n = fmaf(a1.x, a1.x, n);
    n = fmaf(a1.y, a1.y, n);
    n = fmaf(a1.z, a1.z, n);
    n = fmaf(a1.w, a1.w, n);
    return n;
}

// ---- packed weight tables: built on device, then copied into __constant__ ----
struct __align__(16) CTab {
    ulonglong2 W1[32];   // (w0,w0 | w1,w1)
    ulonglong2 BW[32];   // (b1,b1 | 0.5*w2c,0.5*w2c)
    ulonglong2 W2[32];   // (0.5*w2a,.. | 0.5*w2b,..)
    U64        B2[3];    // (b2k, b2k)
    float      scal[2];  // lam, 1-lam
};

__device__   CTab dScratch;   // written by prep kernel
__constant__ CTab cT;         // read by main kernel (constant port)

__global__ void prep_kernel(const float* __restrict__ W1,
                            const float* __restrict__ b1,
                            const float* __restrict__ W2,
                            const float* __restrict__ b2,
                            const float* __restrict__ alpha)
{
    const int t = threadIdx.x;     // 32 threads
    float w0 = W1[2 * t], w1 = W1[2 * t + 1];
    ulonglong2 q; q.x = pk2(w0, w0); q.y = pk2(w1, w1);
    dScratch.W1[t] = q;
    float bb = b1[t], wc = 0.5f * W2[64 + t];
    ulonglong2 qb; qb.x = pk2(bb, bb); qb.y = pk2(wc, wc);
    dScratch.BW[t] = qb;
    float wa = 0.5f * W2[t], wb = 0.5f * W2[32 + t];
    ulonglong2 q2; q2.x = pk2(wa, wa); q2.y = pk2(wb, wb);
    dScratch.W2[t] = q2;
    if (t == 0) {
        float al  = alpha[0];
        float lam = 1.0f / (1.0f + __expf(-al));
        dScratch.scal[0] = lam;
        dScratch.scal[1] = 1.0f - lam;
        dScratch.B2[0] = pk2(b2[0], b2[0]);
        dScratch.B2[1] = pk2(b2[1], b2[1]);
        dScratch.B2[2] = pk2(b2[2], b2[2]);
    }
}

#define TPB 128          // threads per block
#define OPB 512          // octonions per block (4 per thread)

__global__ __launch_bounds__(TPB, 8)
void g2ff_kernel(const float4* __restrict__ in4,
                 float4*       __restrict__ out4)
{
    const int t = threadIdx.x;
    const int base = blockIdx.x * OPB;
    const int mA = base + t;
    const int mB = base + TPB + t;
    const int mC = base + 2 * TPB + t;
    const int mD = base + 3 * TPB + t;

    // ---- prologue: scalar n^2 per octonion; pack only (r, np) pairs ----
    U64 Xp0, Xnp, Yp0, Ynp;
    {
        float4 a0 = in4[2 * mA + 0];
        float4 a1 = in4[2 * mA + 1];
        float4 b0 = in4[2 * mB + 0];
        float4 b1v = in4[2 * mB + 1];
        float nA = norm2_imag(a0, a1);
        float nB = norm2_imag(b0, b1v);
        Xp0 = pk2(a0.x, b0.x);
        Xnp = pk2(sqrt_ap(nA), sqrt_ap(nB));
    }
    {
        float4 a0 = in4[2 * mC + 0];
        float4 a1 = in4[2 * mC + 1];
        float4 b0 = in4[2 * mD + 0];
        float4 b1v = in4[2 * mD + 1];
        float nA = norm2_imag(a0, a1);
        float nB = norm2_imag(b0, b1v);
        Yp0 = pk2(a0.x, b0.x);
        Ynp = pk2(sqrt_ap(nA), sqrt_ap(nB));
    }

    // GELU-tanh constants
    const U64 C1 = pk2(0.7978845608028654f, 0.7978845608028654f);
    const U64 C2 = pk2(0.035677408136300125f, 0.035677408136300125f);

    U64 aAX = cT.B2[0], aBX = cT.B2[1], aCX = cT.B2[2];
    U64 aAY = cT.B2[0], aBY = cT.B2[1], aCY = cT.B2[2];

#pragma unroll
    for (int j = 0; j < 32; j++) {
        ulonglong2 w1j = cT.W1[j];   // LDC.128 (constant port, off L1tex)
        ulonglong2 bwj = cT.BW[j];
        ulonglong2 w2j = cT.W2[j];

        // stream X:  h' = z*(1+tanh(u)) = 2*gelu(z); W2 tables pre-halved
        {
            U64 z  = fma2(Xnp, w1j.y, fma2(Xp0, w1j.x, bwj.x));
            U64 z2 = mul2(z, z);
            U64 qq = fma2(z2, C2, C1);
            U64 u  = mul2(z, qq);
            float ul, uh; upk2(u, ul, uh);
            U64 tt = pk2(tanh_ap(ul), tanh_ap(uh));
            U64 h  = fma2(z, tt, z);
            aAX = fma2(h, w2j.x, aAX);
            aBX = fma2(h, w2j.y, aBX);
            aCX = fma2(h, bwj.y, aCX);
        }
        // stream Y
        {
            U64 z  = fma2(Ynp, w1j.y, fma2(Yp0, w1j.x, bwj.x));
            U64 z2 = mul2(z, z);
            U64 qq = fma2(z2, C2, C1);
            U64 u  = mul2(z, qq);
            float ul, uh; upk2(u, ul, uh);
            U64 tt = pk2(tanh_ap(ul), tanh_ap(uh));
            U64 h  = fma2(z, tt, z);
            aAY = fma2(h, w2j.x, aAY);
            aBY = fma2(h, w2j.y, aBY);
            aCY = fma2(h, bwj.y, aCY);
        }
    }

    const U64 N1  = pk2(-1.0f, -1.0f);
    const U64 N3  = pk2(-3.0f, -3.0f);
    const U64 TWO = pk2(2.0f, 2.0f);

    const float lam = cT.scal[0], oml = cT.scal[1];
    const U64 LAM = pk2(lam, lam);
    const U64 OML = pk2(oml, oml);

    // ---- epilogue stream X (re-load octonions from global; L2 hit) ----
    {
        U64 n2 = mul2(Xnp, Xnp);              // recompute (np = sqrt(n2))
        U64 r2 = mul2(Xp0, Xp0);
        U64 s2 = fma2(n2, N1, r2);            // r^2 - n^2
        U64 u3 = fma2(n2, N3, r2);            // r^2 - 3n^2
        U64 s3 = mul2(Xp0, u3);
        U64 t3 = fma2(r2, TWO, s2);           // 3r^2 - n^2
        U64 P  = fma2(aAX, Xp0, fma2(aBX, s2, mul2(aCX, s3)));
        U64 tr = add2(Xp0, Xp0);
        U64 Q  = fma2(aCX, t3, fma2(aBX, tr, aAX));
        U64 ss = fma2(mul2(Q, Q), n2, mul2(P, P));
        float sl, sh; upk2(ss, sl, sh);
        sl = fmaxf(sl, 1e-16f);
        sh = fmaxf(sh, 1e-16f);
        U64 inv = pk2(rsqrt_ap(sl), rsqrt_ap(sh));
        U64 li  = mul2(LAM, inv);
        U64 K   = fma2(li, Q, OML);
        U64 o0  = fma2(li, P, mul2(Xp0, OML));

        float Klo, Khi; upk2(K, Klo, Khi);
        float olo, ohi; upk2(o0, olo, ohi);

        float4 a0 = in4[2 * mA + 0];
        float4 a1 = in4[2 * mA + 1];
        a0.x = olo;
        a0.y *= Klo; a0.z *= Klo; a0.w *= Klo;
        a1.x *= Klo; a1.y *= Klo; a1.z *= Klo; a1.w *= Klo;
        out4[2 * mA + 0] = a0;
        out4[2 * mA + 1] = a1;

        float4 b0 = in4[2 * mB + 0];
        float4 b1v = in4[2 * mB + 1];
        b0.x = ohi;
        b0.y *= Khi; b0.z *= Khi; b0.w *= Khi;
        b1v.x *= Khi; b1v.y *= Khi; b1v.z *= Khi; b1v.w *= Khi;
        out4[2 * mB + 0] = b0;
        out4[2 * mB + 1] = b1v;
    }
    // ---- epilogue stream Y ----
    {
        U64 n2 = mul2(Ynp, Ynp);
        U64 r2 = mul2(Yp0, Yp0);
        U64 s2 = fma2(n2, N1, r2);
        U64 u3 = fma2(n2, N3, r2);
        U64 s3 = mul2(Yp0, u3);
        U64 t3 = fma2(r2, TWO, s2);
        U64 P  = fma2(aAY, Yp0, fma2(aBY, s2, mul2(aCY, s3)));
        U64 tr = add2(Yp0, Yp0);
        U64 Q  = fma2(aCY, t3, fma2(aBY, tr, aAY));
        U64 ss = fma2(mul2(Q, Q), n2, mul2(P, P));
        float sl, sh; upk2(ss, sl, sh);
        sl = fmaxf(sl, 1e-16f);
        sh = fmaxf(sh, 1e-16f);
        U64 inv = pk2(rsqrt_ap(sl), rsqrt_ap(sh));
        U64 li  = mul2(LAM, inv);
        U64 K   = fma2(li, Q, OML);
        U64 o0  = fma2(li, P, mul2(Yp0, OML));

        float Klo, Khi; upk2(K, Klo, Khi);
        float olo, ohi; upk2(o0, olo, ohi);

        float4 a0 = in4[2 * mC + 0];
        float4 a1 = in4[2 * mC + 1];
        a0.x = olo;
        a0.y *= Klo; a0.z *= Klo; a0.w *= Klo;
        a1.x *= Klo; a1.y *= Klo; a1.z *= Klo; a1.w *= Klo;
        out4[2 * mC + 0] = a0;
        out4[2 * mC + 1] = a1;

        float4 b0 = in4[2 * mD + 0];
        float4 b1v = in4[2 * mD + 1];
        b0.x = ohi;
        b0.y *= Khi; b0.z *= Khi; b0.w *= Khi;
        b1v.x *= Khi; b1v.y *= Khi; b1v.z *= Khi; b1v.w *= Khi;
        out4[2 * mD + 0] = b0;
        out4[2 * mD + 1] = b1v;
    }
}

extern "C" void kernel_launch(void* const* d_in, const int* in_sizes, int n_in,
                              void* d_out, int out_size)
{
    const float* o     = (const float*)d_in[0];
    const float* W1    = (const float*)d_in[1];
    const float* b1    = (const float*)d_in[2];
    const float* W2    = (const float*)d_in[3];
    const float* b2    = (const float*)d_in[4];
    const float* alpha = (const float*)d_in[5];

    // 1) pack weight tables on device
    prep_kernel<<<1, 32>>>(W1, b1, W2, b2, alpha);

    // 2) copy packed tables into __constant__ (D2D memcpy node, capturable)
    void* scratch_addr = nullptr;
    cudaGetSymbolAddress(&scratch_addr, dScratch);
    cudaMemcpyToSymbolAsync(cT, scratch_addr, sizeof(CTab), 0,
                            cudaMemcpyDeviceToDevice);

    // 3) main kernel
    const int total = in_sizes[0];          // 33,554,432 floats
    const int octs  = total / 8;            // 4,194,304 octonions
    const int blocks = octs / OPB;          // 8192

    g2ff_kernel<<<blocks, TPB>>>((const float4*)o, (float4*)d_out);
}

// round 17
// speedup vs baseline: 1.1377x; 1.0353x over previous
#include <cuda_runtime.h>
#include <cuda_bf16.h>

// ---------------------------------------------------------------------------
// G2EquivariantFeedForward, GB300 sm_103a — round 17
//
// Closed form: for octonion x = r + v (v pure imaginary),
//   x^2 = (r^2 - n^2, 2r v),  x^3 = (r(r^2-3n^2), (3r^2-n^2) v),  n^2 = |v|^2
//   upd = a x + b x^2 + c x^3 = (P, Q v)
//   P = a r + b (r^2-n^2) + c r (r^2-3n^2)
//   Q = a + 2 b r + c (3r^2-n^2),       |upd|^2 = P^2 + Q^2 n^2
//
// Main kernel = round 8 exactly (measured best, reproduced twice at
// 52.7/52.8us): NS=2 f32x2 streams, full unroll, constant-port splat
// tables, tanh-GELU with 0.5 folded into W2, scalar epilogue with global
// re-load, __launch_bounds__(128,8).
//
// New this round: prep kernel writes the packed tables DIRECTLY into the
// __constant__ symbol through its device address (constant storage is
// ordinary device memory; the per-SM constant cache is invalidated at
// launch boundaries, so the next kernel's LDC reads see the new data).
// This deletes the cudaMemcpyToSymbolAsync graph node + dScratch copy —
// shrinking the fixed ~5-7us prep/copy tax without touching the main
// kernel's schedule.
// ---------------------------------------------------------------------------

typedef unsigned long long U64;

__device__ __forceinline__ U64 pk2(float lo, float hi) {
    U64 r; asm("mov.b64 %0, {%1, %2};" : "=l"(r) : "f"(lo), "f"(hi)); return r;
}
__device__ __forceinline__ void upk2(U64 v, float& lo, float& hi) {
    asm("mov.b64 {%0, %1}, %2;" : "=f"(lo), "=f"(hi) : "l"(v));
}
__device__ __forceinline__ U64 fma2(U64 a, U64 b, U64 c) {
    U64 d; asm("fma.rn.f32x2 %0, %1, %2, %3;" : "=l"(d) : "l"(a), "l"(b), "l"(c)); return d;
}
__device__ __forceinline__ U64 mul2(U64 a, U64 b) {
    U64 d; asm("mul.rn.f32x2 %0, %1, %2;" : "=l"(d) : "l"(a), "l"(b)); return d;
}
__device__ __forceinline__ U64 add2(U64 a, U64 b) {
    U64 d; asm("add.rn.f32x2 %0, %1, %2;" : "=l"(d) : "l"(a), "l"(b)); return d;
}
__device__ __forceinline__ float tanh_ap(float x) {
    float t; asm("tanh.approx.f32 %0, %1;" : "=f"(t) : "f"(x)); return t;
}
__device__ __forceinline__ float sqrt_ap(float x) {
    float t; asm("sqrt.approx.f32 %0, %1;" : "=f"(t) : "f"(x)); return t;
}
__device__ __forceinline__ float rsqrt_ap(float x) {
    float t; asm("rsqrt.approx.f32 %0, %1;" : "=f"(t) : "f"(x)); return t;
}

__device__ __forceinline__ float norm2_imag(const float4& a0, const float4& a1) {
    float n = a0.y * a0.y;
    n = fmaf(a0.z, a0.z, n);
    n = fmaf(a0.w, a0.w, n);
    n = fmaf(a1.x, a1.x, n);
    n = fmaf(a1.y, a1.y, n);
    n = fmaf(a1.z, a1.z, n);
    n = fmaf(a1.w, a1.w, n);
    return n;
}

// ---- packed weight tables in __constant__; written in-place by prep ----
struct __align__(16) CTab {
    ulonglong2 W1[32];   // (w0,w0 | w1,w1)
    ulonglong2 BW[32];   // (b1,b1 | 0.5*w2c,0.5*w2c)
    ulonglong2 W2[32];   // (0.5*w2a,.. | 0.5*w2b,..)
    U64        B2[3];    // (b2k, b2k)
    float      scal[2];  // lam, 1-lam
};

__constant__ CTab cT;    // read via constant port by main kernel

// Writes packed tables straight into the __constant__ symbol's backing
// store (device memory) through the pointer passed from the host.
__global__ void prep_kernel(const float* __restrict__ W1,
                            const float* __restrict__ b1,
                            const float* __restrict__ W2,
                            const float* __restrict__ b2,
                            const float* __restrict__ alpha,
                            CTab* __restrict__ out)
{
    const int t = threadIdx.x;     // 32 threads
    float w0 = W1[2 * t], w1 = W1[2 * t + 1];
    ulonglong2 q; q.x = pk2(w0, w0); q.y = pk2(w1, w1);
    out->W1[t] = q;
    float bb = b1[t], wc = 0.5f * W2[64 + t];
    ulonglong2 qb; qb.x = pk2(bb, bb); qb.y = pk2(wc, wc);
    out->BW[t] = qb;
    float wa = 0.5f * W2[t], wb = 0.5f * W2[32 + t];
    ulonglong2 q2; q2.x = pk2(wa, wa); q2.y = pk2(wb, wb);
    out->W2[t] = q2;
    if (t == 0) {
        float al  = alpha[0];
        float lam = 1.0f / (1.0f + __expf(-al));
        out->scal[0] = lam;
        out->scal[1] = 1.0f - lam;
        out->B2[0] = pk2(b2[0], b2[0]);
        out->B2[1] = pk2(b2[1], b2[1]);
        out->B2[2] = pk2(b2[2], b2[2]);
    }
}

#define TPB 128          // threads per block
#define OPB 512          // octonions per block (4 per thread)

__global__ __launch_bounds__(TPB, 8)
void g2ff_kernel(const float4* __restrict__ in4,
                 float4*       __restrict__ out4)
{
    const int t = threadIdx.x;
    const int base = blockIdx.x * OPB;
    const int mA = base + t;
    const int mB = base + TPB + t;
    const int mC = base + 2 * TPB + t;
    const int mD = base + 3 * TPB + t;

    // ---- prologue: scalar n^2 per octonion; pack only (r, np) pairs ----
    U64 Xp0, Xnp, Yp0, Ynp;
    {
        float4 a0 = in4[2 * mA + 0];
        float4 a1 = in4[2 * mA + 1];
        float4 b0 = in4[2 * mB + 0];
        float4 b1v = in4[2 * mB + 1];
        float nA = norm2_imag(a0, a1);
        float nB = norm2_imag(b0, b1v);
        Xp0 = pk2(a0.x, b0.x);
        Xnp = pk2(sqrt_ap(nA), sqrt_ap(nB));
    }
    {
        float4 a0 = in4[2 * mC + 0];
        float4 a1 = in4[2 * mC + 1];
        float4 b0 = in4[2 * mD + 0];
        float4 b1v = in4[2 * mD + 1];
        float nA = norm2_imag(a0, a1);
        float nB = norm2_imag(b0, b1v);
        Yp0 = pk2(a0.x, b0.x);
        Ynp = pk2(sqrt_ap(nA), sqrt_ap(nB));
    }

    // GELU-tanh constants
    const U64 C1 = pk2(0.7978845608028654f, 0.7978845608028654f);
    const U64 C2 = pk2(0.035677408136300125f, 0.035677408136300125f);

    U64 aAX = cT.B2[0], aBX = cT.B2[1], aCX = cT.B2[2];
    U64 aAY = cT.B2[0], aBY = cT.B2[1], aCY = cT.B2[2];

#pragma unroll
    for (int j = 0; j < 32; j++) {
        ulonglong2 w1j = cT.W1[j];   // LDC.128 (constant port, off L1tex)
        ulonglong2 bwj = cT.BW[j];
        ulonglong2 w2j = cT.W2[j];

        // stream X:  h' = z*(1+tanh(u)) = 2*gelu(z); W2 tables pre-halved
        {
            U64 z  = fma2(Xnp, w1j.y, fma2(Xp0, w1j.x, bwj.x));
            U64 z2 = mul2(z, z);
            U64 qq = fma2(z2, C2, C1);
            U64 u  = mul2(z, qq);
            float ul, uh; upk2(u, ul, uh);
            U64 tt = pk2(tanh_ap(ul), tanh_ap(uh));
            U64 h  = fma2(z, tt, z);
            aAX = fma2(h, w2j.x, aAX);
            aBX = fma2(h, w2j.y, aBX);
            aCX = fma2(h, bwj.y, aCX);
        }
        // stream Y
        {
            U64 z  = fma2(Ynp, w1j.y, fma2(Yp0, w1j.x, bwj.x));
            U64 z2 = mul2(z, z);
            U64 qq = fma2(z2, C2, C1);
            U64 u  = mul2(z, qq);
            float ul, uh; upk2(u, ul, uh);
            U64 tt = pk2(tanh_ap(ul), tanh_ap(uh));
            U64 h  = fma2(z, tt, z);
            aAY = fma2(h, w2j.x, aAY);
            aBY = fma2(h, w2j.y, aBY);
            aCY = fma2(h, bwj.y, aCY);
        }
    }

    const U64 N1  = pk2(-1.0f, -1.0f);
    const U64 N3  = pk2(-3.0f, -3.0f);
    const U64 TWO = pk2(2.0f, 2.0f);

    const float lam = cT.scal[0], oml = cT.scal[1];
    const U64 LAM = pk2(lam, lam);
    const U64 OML = pk2(oml, oml);

    // ---- epilogue stream X (re-load octonions from global; L2 hit) ----
    {
        U64 n2 = mul2(Xnp, Xnp);              // recompute (np = sqrt(n2))
        U64 r2 = mul2(Xp0, Xp0);
        U64 s2 = fma2(n2, N1, r2);            // r^2 - n^2
        U64 u3 = fma2(n2, N3, r2);            // r^2 - 3n^2
        U64 s3 = mul2(Xp0, u3);
        U64 t3 = fma2(r2, TWO, s2);           // 3r^2 - n^2
        U64 P  = fma2(aAX, Xp0, fma2(aBX, s2, mul2(aCX, s3)));
        U64 tr = add2(Xp0, Xp0);
        U64 Q  = fma2(aCX, t3, fma2(aBX, tr, aAX));
        U64 ss = fma2(mul2(Q, Q), n2, mul2(P, P));
        float sl, sh; upk2(ss, sl, sh);
        sl = fmaxf(sl, 1e-16f);
        sh = fmaxf(sh, 1e-16f);
        U64 inv = pk2(rsqrt_ap(sl), rsqrt_ap(sh));
        U64 li  = mul2(LAM, inv);
        U64 K   = fma2(li, Q, OML);
        U64 o0  = fma2(li, P, mul2(Xp0, OML));

        float Klo, Khi; upk2(K, Klo, Khi);
        float olo, ohi; upk2(o0, olo, ohi);

        float4 a0 = in4[2 * mA + 0];
        float4 a1 = in4[2 * mA + 1];
        a0.x = olo;
        a0.y *= Klo; a0.z *= Klo; a0.w *= Klo;
        a1.x *= Klo; a1.y *= Klo; a1.z *= Klo; a1.w *= Klo;
        out4[2 * mA + 0] = a0;
        out4[2 * mA + 1] = a1;

        float4 b0 = in4[2 * mB + 0];
        float4 b1v = in4[2 * mB + 1];
        b0.x = ohi;
        b0.y *= Khi; b0.z *= Khi; b0.w *= Khi;
        b1v.x *= Khi; b1v.y *= Khi; b1v.z *= Khi; b1v.w *= Khi;
        out4[2 * mB + 0] = b0;
        out4[2 * mB + 1] = b1v;
    }
    // ---- epilogue stream Y ----
    {
        U64 n2 = mul2(Ynp, Ynp);
        U64 r2 = mul2(Yp0, Yp0);
        U64 s2 = fma2(n2, N1, r2);
        U64 u3 = fma2(n2, N3, r2);
        U64 s3 = mul2(Yp0, u3);
        U64 t3 = fma2(r2, TWO, s2);
        U64 P  = fma2(aAY, Yp0, fma2(aBY, s2, mul2(aCY, s3)));
        U64 tr = add2(Yp0, Yp0);
        U64 Q  = fma2(aCY, t3, fma2(aBY, tr, aAY));
        U64 ss = fma2(mul2(Q, Q), n2, mul2(P, P));
        float sl, sh; upk2(ss, sl, sh);
        sl = fmaxf(sl, 1e-16f);
        sh = fmaxf(sh, 1e-16f);
        U64 inv = pk2(rsqrt_ap(sl), rsqrt_ap(sh));
        U64 li  = mul2(LAM, inv);
        U64 K   = fma2(li, Q, OML);
        U64 o0  = fma2(li, P, mul2(Yp0, OML));

        float Klo, Khi; upk2(K, Klo, Khi);
        float olo, ohi; upk2(o0, olo, ohi);

        float4 a0 = in4[2 * mC + 0];
        float4 a1 = in4[2 * mC + 1];
        a0.x = olo;
        a0.y *= Klo; a0.z *= Klo; a0.w *= Klo;
        a1.x *= Klo; a1.y *= Klo; a1.z *= Klo; a1.w *= Klo;
        out4[2 * mC + 0] = a0;
        out4[2 * mC + 1] = a1;

        float4 b0 = in4[2 * mD + 0];
        float4 b1v = in4[2 * mD + 1];
        b0.x = ohi;
        b0.y *= Khi; b0.z *= Khi; b0.w *= Khi;
        b1v.x *= Khi; b1v.y *= Khi; b1v.z *= Khi; b1v.w *= Khi;
        out4[2 * mD + 0] = b0;
        out4[2 * mD + 1] = b1v;
    }
}

extern "C" void kernel_launch(void* const* d_in, const int* in_sizes, int n_in,
                              void* d_out, int out_size)
{
    const float* o     = (const float*)d_in[0];
    const float* W1    = (const float*)d_in[1];
    const float* b1    = (const float*)d_in[2];
    const float* W2    = (const float*)d_in[3];
    const float* b2    = (const float*)d_in[4];
    const float* alpha = (const float*)d_in[5];

    // 1) pack weight tables directly into the __constant__ symbol's backing
    //    store (constant cache is invalidated at the next launch boundary,
    //    so g2ff_kernel's LDC reads see the new data). No memcpy node.
    void* ct_addr = nullptr;
    cudaGetSymbolAddress(&ct_addr, cT);
    prep_kernel<<<1, 32>>>(W1, b1, W2, b2, alpha, (CTab*)ct_addr);

    // 2) main kernel (byte-identical to round 8's)
    const int total = in_sizes[0];          // 33,554,432 floats
    const int octs  = total / 8;            // 4,194,304 octonions
    const int blocks = octs / OPB;          // 8192

    g2ff_kernel<<<blocks, TPB>>>((const float4*)o, (float4*)d_out);
}